// round 2
// baseline (speedup 1.0000x reference)
#include <cuda_runtime.h>
#include <math_constants.h>

// Imputer: x[B,D,N,S], B=64, D=2, N=2048, S=128 fp32.
// For each (b,n): d* = first d whose row has any -inf; mean = mean of valid
// entries of row (b,d*,n,:); every -inf at (b,*,n,*) replaced by mean.
//
// R2: one warp handles TWO (b,n) pairs -> 4 float4 loads issued back-to-back
// (MLP=4), two independent reductions interleaved through one shfl chain,
// counts reduced with a single REDUX.SYNC.ADD.

#define B_ 64
#define D_ 2
#define N_ 2048
#define S_ 128

__global__ void __launch_bounds__(256) imputer_kernel(
    const float4* __restrict__ x, float4* __restrict__ out)
{
    const unsigned gtid = blockIdx.x * blockDim.x + threadIdx.x;
    const unsigned warp = gtid >> 5;
    const unsigned lane = gtid & 31u;

    const unsigned qA = warp * 2u;          // pair indices (b*N + n)
    const unsigned qB = qA + 1u;
    if (qA >= B_ * N_) return;

    const unsigned row_f4  = S_ / 4;               // 32
    const unsigned dstride = (N_ * S_) / 4;        // 65536

    const unsigned bA = qA >> 11, nA = qA & (N_ - 1);
    const unsigned bB = qB >> 11, nB = qB & (N_ - 1);

    const unsigned a0 = bA * (D_ * dstride) + nA * row_f4 + lane;
    const unsigned a1 = a0 + dstride;
    const unsigned b0 = bB * (D_ * dstride) + nB * row_f4 + lane;
    const unsigned b1 = b0 + dstride;

    // issue all 4 loads before any dependent work
    float4 vA0 = x[a0];
    float4 vA1 = x[a1];
    float4 vB0 = x[b0];
    float4 vB1 = x[b1];

    const float NEG_INF = -CUDART_INF_F;

    float sA0 = 0.f, sA1 = 0.f, sB0 = 0.f, sB1 = 0.f;
    int   cA0 = 0,   cA1 = 0,   cB0 = 0,   cB1 = 0;
    bool  mA0 = false, mB0 = false;

    #define ACC(v, comp, S, C)                        \
        do { float t = (v).comp;                      \
             if (t != NEG_INF) { S += t; C += 1; } } while (0)
    #define ACCM(v, comp, S, C, M)                    \
        do { float t = (v).comp;                      \
             if (t == NEG_INF) { M = true; }          \
             else { S += t; C += 1; } } while (0)

    ACCM(vA0, x, sA0, cA0, mA0); ACCM(vA0, y, sA0, cA0, mA0);
    ACCM(vA0, z, sA0, cA0, mA0); ACCM(vA0, w, sA0, cA0, mA0);
    ACC (vA1, x, sA1, cA1);      ACC (vA1, y, sA1, cA1);
    ACC (vA1, z, sA1, cA1);      ACC (vA1, w, sA1, cA1);
    ACCM(vB0, x, sB0, cB0, mB0); ACCM(vB0, y, sB0, cB0, mB0);
    ACCM(vB0, z, sB0, cB0, mB0); ACCM(vB0, w, sB0, cB0, mB0);
    ACC (vB1, x, sB1, cB1);      ACC (vB1, y, sB1, cB1);
    ACC (vB1, z, sB1, cB1);      ACC (vB1, w, sB1, cB1);
    #undef ACC
    #undef ACCM

    // d* = 0 if row 0 has any missing else 1 (mean unused if no missing at all;
    // all-missing selected row -> 0/max(0,1)=0, matching reference).
    const bool useA0 = (__ballot_sync(0xffffffffu, mA0) != 0u);
    const bool useB0 = (__ballot_sync(0xffffffffu, mB0) != 0u);

    float sA = useA0 ? sA0 : sA1;
    float sB = useB0 ? sB0 : sB1;
    int   cA = useA0 ? cA0 : cA1;
    int   cB = useB0 ? cB0 : cB1;

    // counts: single-instruction warp reduction
    cA = __reduce_add_sync(0xffffffffu, (unsigned)cA);
    cB = __reduce_add_sync(0xffffffffu, (unsigned)cB);

    // sums: two independent chains interleaved
    #pragma unroll
    for (int o = 16; o > 0; o >>= 1) {
        sA += __shfl_xor_sync(0xffffffffu, sA, o);
        sB += __shfl_xor_sync(0xffffffffu, sB, o);
    }

    const float meanA = sA / fmaxf((float)cA, 1.0f);
    const float meanB = sB / fmaxf((float)cB, 1.0f);

    float4 o0, o1, o2, o3;
    o0.x = (vA0.x == NEG_INF) ? meanA : vA0.x;
    o0.y = (vA0.y == NEG_INF) ? meanA : vA0.y;
    o0.z = (vA0.z == NEG_INF) ? meanA : vA0.z;
    o0.w = (vA0.w == NEG_INF) ? meanA : vA0.w;
    o1.x = (vA1.x == NEG_INF) ? meanA : vA1.x;
    o1.y = (vA1.y == NEG_INF) ? meanA : vA1.y;
    o1.z = (vA1.z == NEG_INF) ? meanA : vA1.z;
    o1.w = (vA1.w == NEG_INF) ? meanA : vA1.w;
    o2.x = (vB0.x == NEG_INF) ? meanB : vB0.x;
    o2.y = (vB0.y == NEG_INF) ? meanB : vB0.y;
    o2.z = (vB0.z == NEG_INF) ? meanB : vB0.z;
    o2.w = (vB0.w == NEG_INF) ? meanB : vB0.w;
    o3.x = (vB1.x == NEG_INF) ? meanB : vB1.x;
    o3.y = (vB1.y == NEG_INF) ? meanB : vB1.y;
    o3.z = (vB1.z == NEG_INF) ? meanB : vB1.z;
    o3.w = (vB1.w == NEG_INF) ? meanB : vB1.w;

    out[a0] = o0;
    out[a1] = o1;
    out[b0] = o2;
    out[b1] = o3;
}

extern "C" void kernel_launch(void* const* d_in, const int* in_sizes, int n_in,
                              void* d_out, int out_size)
{
    (void)in_sizes; (void)n_in; (void)out_size;
    const float4* x   = (const float4*)d_in[0];
    float4*       out = (float4*)d_out;

    const int total_pairs = B_ * N_;              // 131072
    const int warps       = total_pairs / 2;      // 65536
    const int threads     = 256;                  // 8 warps/block
    const int blocks      = (warps * 32) / threads;  // 8192

    imputer_kernel<<<blocks, threads>>>(x, out);
}

// round 3
// speedup vs baseline: 1.0007x; 1.0007x over previous
#include <cuda_runtime.h>
#include <math_constants.h>

// Imputer: x[B,D,N,S], B=64, D=2, N=2048, S=128 fp32.
// For each (b,n): d* = first d whose row has any -inf; mean = mean of valid
// entries of row (b,d*,n,:); every -inf at (b,*,n,*) replaced by mean.
//
// R3: R2 structure (one warp = two (b,n) pairs, MLP=4) + streaming cache
// hints: __ldcs on the zero-reuse input, __stcs on the output, to cut L2
// replacement pressure on the 1:1 read/write stream.

#define B_ 64
#define D_ 2
#define N_ 2048
#define S_ 128

__global__ void __launch_bounds__(256) imputer_kernel(
    const float4* __restrict__ x, float4* __restrict__ out)
{
    const unsigned gtid = blockIdx.x * blockDim.x + threadIdx.x;
    const unsigned warp = gtid >> 5;
    const unsigned lane = gtid & 31u;

    const unsigned qA = warp * 2u;          // pair indices (b*N + n)
    const unsigned qB = qA + 1u;

    const unsigned row_f4  = S_ / 4;               // 32
    const unsigned dstride = (N_ * S_) / 4;        // 65536

    const unsigned bA = qA >> 11, nA = qA & (N_ - 1);
    const unsigned bB = qB >> 11, nB = qB & (N_ - 1);

    const unsigned a0 = bA * (D_ * dstride) + nA * row_f4 + lane;
    const unsigned a1 = a0 + dstride;
    const unsigned b0 = bB * (D_ * dstride) + nB * row_f4 + lane;
    const unsigned b1 = b0 + dstride;

    // issue all 4 loads back-to-back, evict-first (zero reuse)
    float4 vA0 = __ldcs(&x[a0]);
    float4 vA1 = __ldcs(&x[a1]);
    float4 vB0 = __ldcs(&x[b0]);
    float4 vB1 = __ldcs(&x[b1]);

    const float NEG_INF = -CUDART_INF_F;

    float sA0 = 0.f, sA1 = 0.f, sB0 = 0.f, sB1 = 0.f;
    int   cA0 = 0,   cA1 = 0,   cB0 = 0,   cB1 = 0;
    bool  mA0 = false, mB0 = false;

    #define ACC(v, comp, S, C)                        \
        do { float t = (v).comp;                      \
             if (t != NEG_INF) { S += t; C += 1; } } while (0)
    #define ACCM(v, comp, S, C, M)                    \
        do { float t = (v).comp;                      \
             if (t == NEG_INF) { M = true; }          \
             else { S += t; C += 1; } } while (0)

    ACCM(vA0, x, sA0, cA0, mA0); ACCM(vA0, y, sA0, cA0, mA0);
    ACCM(vA0, z, sA0, cA0, mA0); ACCM(vA0, w, sA0, cA0, mA0);
    ACC (vA1, x, sA1, cA1);      ACC (vA1, y, sA1, cA1);
    ACC (vA1, z, sA1, cA1);      ACC (vA1, w, sA1, cA1);
    ACCM(vB0, x, sB0, cB0, mB0); ACCM(vB0, y, sB0, cB0, mB0);
    ACCM(vB0, z, sB0, cB0, mB0); ACCM(vB0, w, sB0, cB0, mB0);
    ACC (vB1, x, sB1, cB1);      ACC (vB1, y, sB1, cB1);
    ACC (vB1, z, sB1, cB1);      ACC (vB1, w, sB1, cB1);
    #undef ACC
    #undef ACCM

    // d* = 0 if row 0 has any missing else 1 (mean unused if no missing at all;
    // all-missing selected row -> 0/max(0,1)=0, matching reference).
    const bool useA0 = (__ballot_sync(0xffffffffu, mA0) != 0u);
    const bool useB0 = (__ballot_sync(0xffffffffu, mB0) != 0u);

    float sA = useA0 ? sA0 : sA1;
    float sB = useB0 ? sB0 : sB1;
    int   cA = useA0 ? cA0 : cA1;
    int   cB = useB0 ? cB0 : cB1;

    // counts: single-instruction warp reduction
    cA = __reduce_add_sync(0xffffffffu, (unsigned)cA);
    cB = __reduce_add_sync(0xffffffffu, (unsigned)cB);

    // sums: two independent chains interleaved
    #pragma unroll
    for (int o = 16; o > 0; o >>= 1) {
        sA += __shfl_xor_sync(0xffffffffu, sA, o);
        sB += __shfl_xor_sync(0xffffffffu, sB, o);
    }

    const float meanA = sA / fmaxf((float)cA, 1.0f);
    const float meanB = sB / fmaxf((float)cB, 1.0f);

    float4 o0, o1, o2, o3;
    o0.x = (vA0.x == NEG_INF) ? meanA : vA0.x;
    o0.y = (vA0.y == NEG_INF) ? meanA : vA0.y;
    o0.z = (vA0.z == NEG_INF) ? meanA : vA0.z;
    o0.w = (vA0.w == NEG_INF) ? meanA : vA0.w;
    o1.x = (vA1.x == NEG_INF) ? meanA : vA1.x;
    o1.y = (vA1.y == NEG_INF) ? meanA : vA1.y;
    o1.z = (vA1.z == NEG_INF) ? meanA : vA1.z;
    o1.w = (vA1.w == NEG_INF) ? meanA : vA1.w;
    o2.x = (vB0.x == NEG_INF) ? meanB : vB0.x;
    o2.y = (vB0.y == NEG_INF) ? meanB : vB0.y;
    o2.z = (vB0.z == NEG_INF) ? meanB : vB0.z;
    o2.w = (vB0.w == NEG_INF) ? meanB : vB0.w;
    o3.x = (vB1.x == NEG_INF) ? meanB : vB1.x;
    o3.y = (vB1.y == NEG_INF) ? meanB : vB1.y;
    o3.z = (vB1.z == NEG_INF) ? meanB : vB1.z;
    o3.w = (vB1.w == NEG_INF) ? meanB : vB1.w;

    __stcs(&out[a0], o0);
    __stcs(&out[a1], o1);
    __stcs(&out[b0], o2);
    __stcs(&out[b1], o3);
}

extern "C" void kernel_launch(void* const* d_in, const int* in_sizes, int n_in,
                              void* d_out, int out_size)
{
    (void)in_sizes; (void)n_in; (void)out_size;
    const float4* x   = (const float4*)d_in[0];
    float4*       out = (float4*)d_out;

    const int total_pairs = B_ * N_;              // 131072
    const int warps       = total_pairs / 2;      // 65536
    const int threads     = 256;                  // 8 warps/block
    const int blocks      = (warps * 32) / threads;  // 8192, exact cover

    imputer_kernel<<<blocks, threads>>>(x, out);
}